// round 1
// baseline (speedup 1.0000x reference)
#include <cuda_runtime.h>

// bg: (1, 4, 32, 32, 32, 16) float32  -> d_in[0], 2,097,152 elems
// gm: (1, 1, 128, 128, 128) float32   -> d_in[1], 2,097,152 elems
// out: (1, 4, 128, 128, 128) float32  -> 8,388,608 elems

#define BH 32   // grid h
#define BW 32   // grid w
#define BD 32   // grid d
#define UP 16   // grid "up" (t) dim
#define NC 4    // channels
#define G  128  // guidance / output spatial dim

#define NVOX (G * G * G)                 // 2,097,152
#define BG_SPATIAL (BH * BW * BD * UP)   // 524,288

// Scratch: channel-last transposed grid, layout [x][y][z][t][c], c contiguous.
// 32*32*32*16*4 floats = 8.39 MB. Static device global (no allocation).
__device__ float g_bgT[BG_SPATIAL * NC];

// ---------------------------------------------------------------------------
// Kernel 1: transpose (c, x, y, z, t) -> (x, y, z, t, c) so the 4 channels of
// one (corner, t) sample become a single float4 load in the slice kernel.
// ---------------------------------------------------------------------------
__global__ void bgT_transpose_kernel(const float* __restrict__ bg) {
    int idx = blockIdx.x * blockDim.x + threadIdx.x;  // over (x,y,z,t) flat
    if (idx >= BG_SPATIAL) return;
    float4 v;
    v.x = __ldg(&bg[0 * BG_SPATIAL + idx]);
    v.y = __ldg(&bg[1 * BG_SPATIAL + idx]);
    v.z = __ldg(&bg[2 * BG_SPATIAL + idx]);
    v.w = __ldg(&bg[3 * BG_SPATIAL + idx]);
    reinterpret_cast<float4*>(g_bgT)[idx] = v;
}

// ---------------------------------------------------------------------------
// Kernel 2: slice. One thread = one output voxel, all 4 channels.
// 8 spatial corners x 2 t-samples = 16 x LDG.128 from g_bgT (L1/L2 resident),
// quadri-linear weights, 4 coalesced scalar stores.
// ---------------------------------------------------------------------------
__global__ __launch_bounds__(256)
void bgrid_slice_kernel(const float* __restrict__ gm, float* __restrict__ out) {
    int idx = blockIdx.x * blockDim.x + threadIdx.x;
    if (idx >= NVOX) return;

    int gd = idx & (G - 1);
    int gw = (idx >> 7) & (G - 1);
    int gh = idx >> 14;

    // Match reference exactly: scale = f32(size-1)/f32(gsize-1), mul in f32,
    // clamp to [0, size-1], floor, i1 = min(i0+1, size-1).
    const float s = 31.0f / 127.0f;  // same for h, w, d (32-grid / 128-guide)

    float x = fminf(fmaxf((float)gh * s, 0.0f), 31.0f);
    float y = fminf(fmaxf((float)gw * s, 0.0f), 31.0f);
    float z = fminf(fmaxf((float)gd * s, 0.0f), 31.0f);

    int   x0 = (int)floorf(x);  float fx = x - (float)x0;  int x1 = min(x0 + 1, BH - 1);
    int   y0 = (int)floorf(y);  float fy = y - (float)y0;  int y1 = min(y0 + 1, BW - 1);
    int   z0 = (int)floorf(z);  float fz = z - (float)z0;  int z1 = min(z0 + 1, BD - 1);

    float g = __ldg(&gm[idx]);
    float t = fminf(fmaxf(g * (float)(UP - 1), 0.0f), (float)(UP - 1));
    int   t0 = (int)floorf(t);  float ft = t - (float)t0;  int t1 = min(t0 + 1, UP - 1);
    float wt0 = 1.0f - ft, wt1 = ft;

    int   xi[2] = { x0, x1 };   float wx[2] = { 1.0f - fx, fx };
    int   yi[2] = { y0, y1 };   float wy[2] = { 1.0f - fy, fy };
    int   zi[2] = { z0, z1 };   float wz[2] = { 1.0f - fz, fz };

    const float4* bgT4 = reinterpret_cast<const float4*>(g_bgT);

    float ax = 0.0f, ay = 0.0f, az = 0.0f, aw = 0.0f;

#pragma unroll
    for (int a = 0; a < 2; a++) {
#pragma unroll
        for (int b = 0; b < 2; b++) {
#pragma unroll
            for (int cc = 0; cc < 2; cc++) {
                float w = wx[a] * wy[b] * wz[cc];
                const float4* base =
                    bgT4 + (((xi[a] * BW + yi[b]) * BD + zi[cc]) * UP);
                float4 v0 = __ldg(base + t0);
                float4 v1 = __ldg(base + t1);
                float w0 = w * wt0, w1 = w * wt1;
                ax += w0 * v0.x + w1 * v1.x;
                ay += w0 * v0.y + w1 * v1.y;
                az += w0 * v0.z + w1 * v1.z;
                aw += w0 * v0.w + w1 * v1.w;
            }
        }
    }

    out[idx]             = ax;
    out[idx + NVOX]      = ay;
    out[idx + 2 * NVOX]  = az;
    out[idx + 3 * NVOX]  = aw;
}

extern "C" void kernel_launch(void* const* d_in, const int* in_sizes, int n_in,
                              void* d_out, int out_size) {
    const float* bg = (const float*)d_in[0];
    const float* gm = (const float*)d_in[1];
    float* out = (float*)d_out;

    (void)in_sizes; (void)n_in; (void)out_size;

    bgT_transpose_kernel<<<(BG_SPATIAL + 255) / 256, 256>>>(bg);
    bgrid_slice_kernel<<<(NVOX + 255) / 256, 256>>>(gm, out);
}